// round 1
// baseline (speedup 1.0000x reference)
#include <cuda_runtime.h>
#include <cuda_bf16.h>

// ---------------------------------------------------------------------------
// GAT layer, fp32 baseline.
//   h   [8,2048,128] f32
//   adj [8,2048,2048] i32 (0/1)
//   W   [128,128] f32  (out_dim, in_dim)
//   a   [256] f32      (a_src = a[0:128], a_dst = a[128:256])
//   out [8,2048,128] f32
//
// out[b,i,:] = sum_j adj * exp(lrelu(s_i + t_j)) * Wh[b,j,:] / Z_i   (0 if Z==0)
// ---------------------------------------------------------------------------

#define BATCH 8
#define NNODE 2048
#define DIM   128
#define NROWS (BATCH * NNODE)   // 16384

__device__ float g_Wh[NROWS * DIM];   // 8 MB scratch
__device__ float g_s[NROWS];
__device__ float g_t[NROWS];

// ---------------------------------------------------------------------------
// Kernel 1: Wh = h @ W^T.  Block = 256 threads computes 32 rows x 128 dims.
// ---------------------------------------------------------------------------
__global__ __launch_bounds__(256) void gat_wh_kernel(
    const float* __restrict__ h, const float* __restrict__ W)
{
    __shared__ float sh_w[128][65];   // [dim][f-chunk], pad 65 for conflict-free
    __shared__ float sh_h[32][65];    // [row][f-chunk]

    const int tid = threadIdx.x;
    const int tx  = tid & 31;         // dim group: dims {tx, tx+32, tx+64, tx+96}
    const int ty  = tid >> 5;         // row group: rows {ty, ty+8, ty+16, ty+24}
    const int row0 = blockIdx.x * 32;

    float acc[4][4];
#pragma unroll
    for (int m = 0; m < 4; m++)
#pragma unroll
        for (int k = 0; k < 4; k++) acc[m][k] = 0.f;

    for (int f0 = 0; f0 < 128; f0 += 64) {
        __syncthreads();
        // load W chunk: 128 dims x 64 f
        for (int k = tid; k < 128 * 64; k += 256) {
            int d = k >> 6, f = k & 63;
            sh_w[d][f] = W[d * 128 + f0 + f];
        }
        // load h chunk: 32 rows x 64 f
        for (int k = tid; k < 32 * 64; k += 256) {
            int r = k >> 6, f = k & 63;
            sh_h[r][f] = h[(row0 + r) * 128 + f0 + f];
        }
        __syncthreads();

#pragma unroll 8
        for (int f = 0; f < 64; ++f) {
            float hv[4], wv[4];
#pragma unroll
            for (int m = 0; m < 4; m++) hv[m] = sh_h[ty + 8 * m][f];
#pragma unroll
            for (int k = 0; k < 4; k++) wv[k] = sh_w[tx + 32 * k][f];
#pragma unroll
            for (int m = 0; m < 4; m++)
#pragma unroll
                for (int k = 0; k < 4; k++) acc[m][k] += hv[m] * wv[k];
        }
    }

#pragma unroll
    for (int m = 0; m < 4; m++)
#pragma unroll
        for (int k = 0; k < 4; k++)
            g_Wh[(row0 + ty + 8 * m) * DIM + tx + 32 * k] = acc[m][k];
}

// ---------------------------------------------------------------------------
// Kernel 1b: s = Wh @ a_src, t = Wh @ a_dst.  One warp per row.
// ---------------------------------------------------------------------------
__global__ __launch_bounds__(256) void gat_st_kernel(const float* __restrict__ a)
{
    const int row  = blockIdx.x * 8 + (threadIdx.x >> 5);
    const int lane = threadIdx.x & 31;

    float4 wv = ((const float4*)(g_Wh + (size_t)row * DIM))[lane];
    float4 as = ((const float4*)a)[lane];
    float4 ad = ((const float4*)a)[lane + 32];

    float sv = wv.x * as.x + wv.y * as.y + wv.z * as.z + wv.w * as.w;
    float tv = wv.x * ad.x + wv.y * ad.y + wv.z * ad.z + wv.w * ad.w;

#pragma unroll
    for (int o = 16; o > 0; o >>= 1) {
        sv += __shfl_down_sync(0xFFFFFFFFu, sv, o);
        tv += __shfl_down_sync(0xFFFFFFFFu, tv, o);
    }
    if (lane == 0) { g_s[row] = sv; g_t[row] = tv; }
}

// ---------------------------------------------------------------------------
// Kernel 2: fused masked-softmax aggregation (no max shift needed; scores
// are bounded). Block = 512 threads = 16 warps = 16 rows; j tiled by 64.
// ---------------------------------------------------------------------------
#define TI 16
#define TJ 64

__global__ __launch_bounds__(512) void gat_attn_kernel(
    const int* __restrict__ adj, float* __restrict__ out)
{
    __shared__ float sh_wh[TJ][DIM];   // 32 KB
    __shared__ float sh_t[TJ];
    __shared__ int   sh_adj[TI][TJ];   // 4 KB

    const int b    = blockIdx.y;
    const int i0   = blockIdx.x * TI;
    const int warp = threadIdx.x >> 5;      // row within tile
    const int lane = threadIdx.x & 31;      // 4 dims: 4*lane .. 4*lane+3
    const int i    = i0 + warp;

    const float s_i = g_s[b * NNODE + i];
    const float* WhB = g_Wh + (size_t)b * NNODE * DIM;
    const int*   adjT = adj + ((size_t)b * NNODE + i0) * NNODE;

    float4 acc = make_float4(0.f, 0.f, 0.f, 0.f);
    float  Z   = 0.f;

    for (int j0 = 0; j0 < NNODE; j0 += TJ) {
        __syncthreads();
        // stage Wh tile (TJ x 128 floats = 2048 float4)
        {
            const float4* src = (const float4*)(WhB + j0 * DIM);
            float4* dst = (float4*)&sh_wh[0][0];
            for (int k = threadIdx.x; k < TJ * (DIM / 4); k += 512)
                dst[k] = src[k];
        }
        // stage t chunk
        if (threadIdx.x < TJ)
            sh_t[threadIdx.x] = g_t[b * NNODE + j0 + threadIdx.x];
        // stage adj tile (TI x TJ ints)
        for (int k = threadIdx.x; k < TI * TJ; k += 512) {
            int r = k / TJ, c = k % TJ;
            sh_adj[r][c] = adjT[(size_t)r * NNODE + j0 + c];
        }
        __syncthreads();

#pragma unroll 4
        for (int jj = 0; jj < TJ; ++jj) {
            if (sh_adj[warp][jj]) {              // warp-uniform branch
                float e = s_i + sh_t[jj];
                e = e > 0.f ? e : 0.2f * e;
                float w = __expf(e);
                Z += w;
                float4 v = *(const float4*)&sh_wh[jj][lane * 4];
                acc.x += w * v.x;
                acc.y += w * v.y;
                acc.z += w * v.z;
                acc.w += w * v.w;
            }
        }
    }

    const float inv = (Z > 0.f) ? (1.f / Z) : 0.f;
    float4 o = make_float4(acc.x * inv, acc.y * inv, acc.z * inv, acc.w * inv);
    *(float4*)(out + ((size_t)b * NNODE + i) * DIM + lane * 4) = o;
}

// ---------------------------------------------------------------------------
extern "C" void kernel_launch(void* const* d_in, const int* in_sizes, int n_in,
                              void* d_out, int out_size)
{
    const float* h   = (const float*)d_in[0];
    const int*   adj = (const int*)  d_in[1];
    const float* W   = (const float*)d_in[2];
    const float* a   = (const float*)d_in[3];
    float*       out = (float*)d_out;

    gat_wh_kernel<<<NROWS / 32, 256>>>(h, W);
    gat_st_kernel<<<NROWS / 8, 256>>>(a);

    dim3 grid(NNODE / TI, BATCH);
    gat_attn_kernel<<<grid, 512>>>(adj, out);
}